// round 9
// baseline (speedup 1.0000x reference)
#include <cuda_runtime.h>
#include <math.h>

#define FULLMASK 0xffffffffu
typedef unsigned long long u64;

static constexpr int NL     = 2048;
static constexpr int NQ     = 16384;
static constexpr int NB     = 2;
static constexpr int H      = 64;
static constexpr int PH     = 256;
static constexpr int COUT   = 3;
static constexpr int KCAP   = 32;
static constexpr int CAP    = 160;
static constexpr int THREADS= 160;   // 5 warps/CTA
static constexpr int WARPS  = 5;
static constexpr int NBLOCK = 592;   // 148 SMs x 4 CTAs -> 20 warps/SM

// decoded scratch (device global: allocation-free)
__device__ float g_dec[NB * NQ * H];   // 8 MB

// ---- main-kernel shared memory layout (float offsets) ----
static constexpr int OFF_W1    = 0;         // 4096  [64][64], j contiguous
static constexpr int OFF_W2    = 4096;      // 4096
static constexpr int OFF_WE0   = 8192;      // 256   [4][64]
static constexpr int OFF_BE0   = 8448;      // 64
static constexpr int OFF_BE1   = 8512;      // 64
static constexpr int OFF_BE2   = 8576;      // 64
static constexpr int OFF_WSW0  = 8640;      // 32
static constexpr int OFF_BSW0  = 8672;      // 16
static constexpr int OFF_WSW1  = 8688;      // 32
static constexpr int OFF_BSW1  = 8720;      // 2 (+6 pad)
static constexpr int OFF_CAND  = 8728;      // 5 warps x 160 u64 = 1600 floats
static constexpr int SMEM_FLOATS = 10328;
static constexpr int SMEM_BYTES  = SMEM_FLOATS * 4;   // 41312 B x4 = 165KB, 63KB L1D left

// ---------- f32x2 packed helpers ----------
__device__ __forceinline__ u64 pk2(float a, float b) {
    u64 r; asm("mov.b64 %0,{%1,%2};" : "=l"(r) : "f"(a), "f"(b)); return r;
}
__device__ __forceinline__ void upk2(u64 v, float& a, float& b) {
    asm("mov.b64 {%0,%1},%2;" : "=f"(a), "=f"(b) : "l"(v));
}
__device__ __forceinline__ u64 f2fma(u64 a, u64 b, u64 c) {
    u64 d; asm("fma.rn.f32x2 %0,%1,%2,%3;" : "=l"(d) : "l"(a), "l"(b), "l"(c)); return d;
}
__device__ __forceinline__ u64 f2mul(u64 a, u64 b) {
    u64 d; asm("mul.rn.f32x2 %0,%1,%2;" : "=l"(d) : "l"(a), "l"(b)); return d;
}
__device__ __forceinline__ u64 f2add(u64 a, u64 b) {
    u64 d; asm("add.rn.f32x2 %0,%1,%2;" : "=l"(d) : "l"(a), "l"(b)); return d;
}
__device__ __forceinline__ unsigned redux_min_u32(unsigned v) {
    unsigned r; asm("redux.sync.min.u32 %0, %1, 0xffffffff;" : "=r"(r) : "r"(v)); return r;
}

// branch-free gelu: A&S 7.1.26 erf (|abs err| <= 1.5e-7)
__device__ __forceinline__ float gelu_f(float x) {
    float z = fabsf(x) * 0.7071067811865476f;
    float t = __fdividef(1.0f, fmaf(0.3275911f, z, 1.0f));
    float p = t * fmaf(t, fmaf(t, fmaf(t, fmaf(t, 1.061405429f, -1.453152027f),
                                        1.421413741f), -0.284496736f), 0.254829592f);
    float e = __expf(-z * z);
    float er = fmaf(-p, e, 1.0f);
    er = copysignf(er, x);
    return 0.5f * x * (1.0f + er);
}

__device__ __forceinline__ void ce(u64& a, u64& b) {
    u64 lo = a < b ? a : b;
    u64 hi = a < b ? b : a;
    a = lo; b = hi;
}

__global__ void __launch_bounds__(THREADS, 4)
magno_kernel(const float* __restrict__ lat,  const float* __restrict__ rnd,
             const float* __restrict__ qry,
             const float* __restrict__ we0,  const float* __restrict__ be0,
             const float* __restrict__ we1,  const float* __restrict__ be1,
             const float* __restrict__ we2,  const float* __restrict__ be2,
             const float* __restrict__ wsw0, const float* __restrict__ bsw0,
             const float* __restrict__ wsw1, const float* __restrict__ bsw1)
{
    extern __shared__ float sm[];
    const int tid = threadIdx.x;

    for (int t = tid; t < H*H;  t += THREADS) sm[OFF_W1+t]  = we1[t];
    for (int t = tid; t < H*H;  t += THREADS) sm[OFF_W2+t]  = we2[t];
    for (int t = tid; t < 4*H;  t += THREADS) sm[OFF_WE0+t] = we0[t];
    for (int t = tid; t < H;    t += THREADS) sm[OFF_BE0+t] = be0[t];
    for (int t = tid; t < H;    t += THREADS) sm[OFF_BE1+t] = be1[t];
    for (int t = tid; t < H;    t += THREADS) sm[OFF_BE2+t] = be2[t];
    if (tid < 32)              sm[OFF_WSW0+tid]    = wsw0[tid];
    if (tid < 16)              sm[OFF_BSW0+tid]    = bsw0[tid];
    if (tid >= 32 && tid < 64) sm[OFF_WSW1+tid-32] = wsw1[tid-32];
    if (tid >= 64 && tid < 66) sm[OFF_BSW1+tid-64] = bsw1[tid-64];
    __syncthreads();

    const int warp = tid >> 5, lane = tid & 31;
    u64* cand = (u64*)(sm + OFF_CAND) + warp * CAP;
    const float2* latf2 = (const float2*)lat;

    const float R0SQ = (float)(0.055 * 0.055);
    const float R1SQ = (float)(0.11  * 0.11);
    const unsigned lt_mask = (1u << lane) - 1u;

    for (int q = blockIdx.x * WARPS + warp; q < NB * NQ; q += gridDim.x * WARPS) {
        const int  bix = q >> 14;
        const float qx = qry[2*q], qy = qry[2*q+1];

        // ---- per-query scale-mixing weights ----
        float s0 = sm[OFF_BSW1+0], s1 = sm[OFF_BSW1+1];
#pragma unroll
        for (int t = 0; t < 16; t++) {
            float z = sm[OFF_BSW0+t] + qx*sm[OFF_WSW0+t] + qy*sm[OFF_WSW0+16+t];
            z = fmaxf(z, 0.0f);
            s0 = fmaf(z, sm[OFF_WSW1+2*t+0], s0);
            s1 = fmaf(z, sm[OFF_WSW1+2*t+1], s1);
        }
        float mx = fmaxf(s0, s1);
        float e0 = __expf(s0 - mx), e1 = __expf(s1 - mx);
        float inv = __fdividef(1.0f, e0 + e1);
        float sw0v = e0 * inv, sw1v = e1 * inv;

        // ---- radius-filtered candidate collection ----
        int cnt = 0;
        for (int l = lane; l < NL; l += 32) {
            float2 y = __ldg(latf2 + l);
            float dx = qx - y.x, dy = qy - y.y;
            float d2 = __fadd_rn(__fmul_rn(dx, dx), __fmul_rn(dy, dy));
            bool pr = d2 <= R1SQ;
            unsigned m = __ballot_sync(FULLMASK, pr);
            if (pr) {
                int pos = cnt + __popc(m & lt_mask);
                if (pos < CAP)
                    cand[pos] = ((u64)__float_as_uint(d2) << 32) | (unsigned)l;
            }
            cnt += __popc(m);
        }
        if (cnt > CAP) cnt = CAP;
        __syncwarp();

        // ---- exact K=32 smallest selection ----
        u64 mykey = 0x7f7fffff00000000ull;
        int nsel;
        if (cnt <= KCAP) {
            nsel = cnt;
            if (lane < cnt) mykey = cand[lane];
        } else {
            nsel = KCAP;
            u64 c0, c1, c2, c3, c4, c5;
            c0 = (lane       < cnt) ? cand[lane      ] : ~0ull;
            c1 = (lane + 32  < cnt) ? cand[lane + 32 ] : ~0ull;
            c2 = (lane + 64  < cnt) ? cand[lane + 64 ] : ~0ull;
            c3 = (lane + 96  < cnt) ? cand[lane + 96 ] : ~0ull;
            c4 = (lane + 128 < cnt) ? cand[lane + 128] : ~0ull;
            c5 = ~0ull;
            ce(c0,c1); ce(c2,c3); ce(c4,c5);
            ce(c0,c2); ce(c3,c5); ce(c1,c4);
            ce(c0,c1); ce(c2,c3); ce(c4,c5);
            ce(c1,c2); ce(c3,c4); ce(c2,c3);

            unsigned hdb = (unsigned)(c0 >> 32);
#pragma unroll 1
            for (int r = 0; r < KCAP; r++) {
                unsigned m = redux_min_u32(hdb);
                unsigned tied = __ballot_sync(FULLMASK, hdb == m);
                int src;
                if ((tied & (tied - 1u)) == 0u) {
                    src = __ffs(tied) - 1;
                } else {
                    unsigned lw = (hdb == m) ? (unsigned)c0 : 0xffffffffu;
                    unsigned mi = redux_min_u32(lw);
                    src = __ffs(__ballot_sync(FULLMASK, lw == mi)) - 1;
                }
                u64 win = __shfl_sync(FULLMASK, c0, src);
                if (lane == r) mykey = win;
                bool pop = (lane == src);
                c0 = pop ? c1 : c0;
                c1 = pop ? c2 : c1;
                c2 = pop ? c3 : c2;
                c3 = pop ? c4 : c3;
                c4 = pop ? c5 : c4;
                c5 = pop ? ~0ull : c5;
                hdb = (unsigned)(c0 >> 32);
            }
        }
        float seld2  = __uint_as_float((unsigned)(mykey >> 32));
        int   selidx = (int)(mykey & 0xffffffffu);
        if (lane >= nsel) { seld2 = 3.4e38f; selidx = 0; }

        bool v0 = (lane < nsel) && (seld2 <= R0SQ);
        int  c0cnt = __popc(__ballot_sync(FULLMASK, v0));
        float coeff = 0.0f;
        if (v0)          coeff += sw0v / (float)(c0cnt > 1 ? c0cnt : 1);
        if (lane < nsel) coeff += sw1v / (float)(nsel  > 1 ? nsel  : 1);

        const float* frowf = rnd + (size_t)(bix * NL + selidx) * H;
        asm volatile("prefetch.global.L1 [%0];" :: "l"(frowf));
        asm volatile("prefetch.global.L1 [%0];" :: "l"(frowf + 32));

        // ---- layer 0 ----
        float h0[64];
        {
            float2 yc = __ldg(latf2 + selidx);
            u64 yx2 = pk2(yc.x, yc.x), yy2 = pk2(yc.y, yc.y);
            u64 qx2 = pk2(qx, qx),     qy2 = pk2(qy, qy);
            const u64* w0r0 = (const u64*)(sm + OFF_WE0);
            const u64* w0r1 = (const u64*)(sm + OFF_WE0 + 64);
            const u64* w0r2 = (const u64*)(sm + OFF_WE0 + 128);
            const u64* w0r3 = (const u64*)(sm + OFF_WE0 + 192);
            const u64* b0p  = (const u64*)(sm + OFF_BE0);
#pragma unroll
            for (int jp = 0; jp < 32; jp++) {
                u64 t = b0p[jp];
                t = f2fma(yx2, w0r0[jp], t);
                t = f2fma(yy2, w0r1[jp], t);
                t = f2fma(qx2, w0r2[jp], t);
                t = f2fma(qy2, w0r3[jp], t);
                float a, b; upk2(t, a, b);
                h0[2*jp]   = gelu_f(a);
                h0[2*jp+1] = gelu_f(b);
            }
        }

        // ---- layer 1 (channel-tiled x2) ----
        float h1[64];
        {
            const ulonglong2* w1 = (const ulonglong2*)(sm + OFF_W1);
#pragma unroll
            for (int t = 0; t < 2; t++) {
                u64 a[16];
                const u64* b1p = (const u64*)(sm + OFF_BE1) + 8*t;
#pragma unroll
                for (int p = 0; p < 16; p++) a[p] = b1p[p];
#pragma unroll 4
                for (int i = 0; i < 64; i++) {
                    u64 hh = pk2(h0[i], h0[i]);
                    const ulonglong2* row = w1 + i*16 + t*8;
#pragma unroll
                    for (int j2 = 0; j2 < 8; j2++) {
                        ulonglong2 w = row[j2];
                        a[2*j2]   = f2fma(hh, w.x, a[2*j2]);
                        a[2*j2+1] = f2fma(hh, w.y, a[2*j2+1]);
                    }
                }
#pragma unroll
                for (int p = 0; p < 16; p++) {
                    float x, y; upk2(a[p], x, y);
                    h1[32*t + 2*p]   = gelu_f(x);
                    h1[32*t + 2*p+1] = gelu_f(y);
                }
            }
        }

        // ---- layer 2 + f(y)*coeff + butterfly reduce-scatter over neighbors ----
        u64 myd = 0;
        {
            u64 cc = pk2(coeff, coeff);
            const float4* frow = (const float4*)frowf;
            const ulonglong2* w2 = (const ulonglong2*)(sm + OFF_W2);
#pragma unroll
            for (int t = 0; t < 2; t++) {
                u64 a[16];
                const u64* b2p = (const u64*)(sm + OFF_BE2) + 8*t;
#pragma unroll
                for (int p = 0; p < 16; p++) a[p] = b2p[p];
#pragma unroll 4
                for (int i = 0; i < 64; i++) {
                    u64 hh = pk2(h1[i], h1[i]);
                    const ulonglong2* row = w2 + i*16 + t*8;
#pragma unroll
                    for (int j2 = 0; j2 < 8; j2++) {
                        ulonglong2 w = row[j2];
                        a[2*j2]   = f2fma(hh, w.x, a[2*j2]);
                        a[2*j2+1] = f2fma(hh, w.y, a[2*j2+1]);
                    }
                }
#pragma unroll
                for (int p2 = 0; p2 < 8; p2++) {
                    float4 f4 = __ldg(frow + 8*t + p2);
                    a[2*p2]   = f2mul(a[2*p2],   f2mul(pk2(f4.x, f4.y), cc));
                    a[2*p2+1] = f2mul(a[2*p2+1], f2mul(pk2(f4.z, f4.w), cc));
                }
                // butterfly reduce-scatter: 16 accs over 32 lanes, 5 stages
                {
                    bool k3 = (lane >> 3) & 1;
#pragma unroll
                    for (int j = 0; j < 8; j++) {
                        u64 sendv = k3 ? a[j] : a[j+8];
                        u64 recv  = __shfl_xor_sync(FULLMASK, sendv, 8);
                        a[j] = f2add(k3 ? a[j+8] : a[j], recv);
                    }
                    bool k2 = (lane >> 2) & 1;
#pragma unroll
                    for (int j = 0; j < 4; j++) {
                        u64 sendv = k2 ? a[j] : a[j+4];
                        u64 recv  = __shfl_xor_sync(FULLMASK, sendv, 4);
                        a[j] = f2add(k2 ? a[j+4] : a[j], recv);
                    }
                    bool k1 = (lane >> 1) & 1;
#pragma unroll
                    for (int j = 0; j < 2; j++) {
                        u64 sendv = k1 ? a[j] : a[j+2];
                        u64 recv  = __shfl_xor_sync(FULLMASK, sendv, 2);
                        a[j] = f2add(k1 ? a[j+2] : a[j], recv);
                    }
                    bool k0 = lane & 1;
                    {
                        u64 sendv = k0 ? a[0] : a[1];
                        u64 recv  = __shfl_xor_sync(FULLMASK, sendv, 1);
                        a[0] = f2add(k0 ? a[1] : a[0], recv);
                    }
                    a[0] = f2add(a[0], __shfl_xor_sync(FULLMASK, a[0], 16));
                    if ((lane >> 4) == t) myd = a[0];
                }
            }
        }
        // coalesced decoded store: lane l -> channels 2l, 2l+1
        ((u64*)g_dec)[(size_t)q * 32 + lane] = myd;
    }
}

// ======== projection kernel: decoded[64] -> gelu(PH=256) -> COUT=3 ========
// 2 threads per row: half = tid&1 handles hidden channels [half*128, half*128+128)
static constexpr int PTHREADS = 128;
static constexpr int PROWS    = PTHREADS / 2;           // 64 rows per block
static constexpr int PGRID    = NB * NQ / PROWS;        // 512

// proj smem layout (floats)
static constexpr int POFF_WP0 = 0;          // 16384  [64][256]
static constexpr int POFF_BP0 = 16384;      // 256
static constexpr int POFF_WP1 = 16640;      // 768    [256][3]
static constexpr int POFF_BP1 = 17408;      // 3 (+1 pad)
static constexpr int PSMEM_FLOATS = 17412;
static constexpr int PSMEM_BYTES  = PSMEM_FLOATS * 4;   // 69648 B -> 3 CTAs/SM

__global__ void __launch_bounds__(PTHREADS)
proj_kernel(const float* __restrict__ wp0, const float* __restrict__ bp0,
            const float* __restrict__ wp1, const float* __restrict__ bp1,
            float* __restrict__ out)
{
    extern __shared__ float psm[];
    const int tid = threadIdx.x;
    for (int t = tid; t < H*PH;    t += PTHREADS) psm[POFF_WP0+t] = wp0[t];
    for (int t = tid; t < PH;      t += PTHREADS) psm[POFF_BP0+t] = bp0[t];
    for (int t = tid; t < PH*COUT; t += PTHREADS) psm[POFF_WP1+t] = wp1[t];
    if (tid < COUT) psm[POFF_BP1+tid] = bp1[tid];
    __syncthreads();

    const int row  = blockIdx.x * PROWS + (tid >> 1);
    const int half = tid & 1;

    // decoded row in registers (both halves need full dec)
    float dec[64];
    {
        const float4* dp = (const float4*)(g_dec + (size_t)row * H);
#pragma unroll
        for (int i = 0; i < 16; i++) {
            float4 v = dp[i];
            dec[4*i+0] = v.x; dec[4*i+1] = v.y;
            dec[4*i+2] = v.z; dec[4*i+3] = v.w;
        }
    }

    float o0 = half ? 0.f : psm[POFF_BP1+0];
    float o1 = half ? 0.f : psm[POFF_BP1+1];
    float o2 = half ? 0.f : psm[POFF_BP1+2];

#pragma unroll 1
    for (int cc = 0; cc < 2; cc++) {             // 2 chunks of 64 hidden per thread
        const int ch = half * 2 + cc;
        u64 a[32];
        {
            const u64* bp = (const u64*)(psm + POFF_BP0 + ch * 64);
#pragma unroll
            for (int p = 0; p < 32; p++) a[p] = bp[p];
        }
#pragma unroll 4
        for (int i = 0; i < 64; i++) {
            u64 dd = pk2(dec[i], dec[i]);
            const ulonglong2* wr =
                (const ulonglong2*)(psm + POFF_WP0 + (size_t)i * PH + ch * 64);
#pragma unroll
            for (int j2 = 0; j2 < 16; j2++) {
                ulonglong2 w = wr[j2];          // LDS.128 broadcast (per half-pair)
                a[2*j2]   = f2fma(dd, w.x, a[2*j2]);
                a[2*j2+1] = f2fma(dd, w.y, a[2*j2+1]);
            }
        }
#pragma unroll
        for (int p = 0; p < 32; p++) {
            float x, y; upk2(a[p], x, y);
            float g0 = gelu_f(x), g1 = gelu_f(y);
            int jj = ch * 64 + 2 * p;
            o0 = fmaf(g0, psm[POFF_WP1 + jj*3 + 0], o0);
            o1 = fmaf(g0, psm[POFF_WP1 + jj*3 + 1], o1);
            o2 = fmaf(g0, psm[POFF_WP1 + jj*3 + 2], o2);
            o0 = fmaf(g1, psm[POFF_WP1 + jj*3 + 3], o0);
            o1 = fmaf(g1, psm[POFF_WP1 + jj*3 + 4], o1);
            o2 = fmaf(g1, psm[POFF_WP1 + jj*3 + 5], o2);
        }
    }

    // combine the two halves (partner = adjacent lane)
    u64 o01 = pk2(o0, o1);
    o01 = f2add(o01, __shfl_xor_sync(FULLMASK, o01, 1));
    o2 += __shfl_xor_sync(FULLMASK, o2, 1);
    if (half == 0) {
        float a, b; upk2(o01, a, b);
        out[row*3 + 0] = a;
        out[row*3 + 1] = b;
        out[row*3 + 2] = o2;
    }
}

extern "C" void kernel_launch(void* const* d_in, const int* in_sizes, int n_in,
                              void* d_out, int out_size) {
    const float* lat  = (const float*)d_in[0];
    const float* rnd  = (const float*)d_in[1];
    const float* qry  = (const float*)d_in[2];
    const float* we0  = (const float*)d_in[3];
    const float* be0  = (const float*)d_in[4];
    const float* we1  = (const float*)d_in[5];
    const float* be1  = (const float*)d_in[6];
    const float* we2  = (const float*)d_in[7];
    const float* be2  = (const float*)d_in[8];
    const float* wsw0 = (const float*)d_in[9];
    const float* bsw0 = (const float*)d_in[10];
    const float* wsw1 = (const float*)d_in[11];
    const float* bsw1 = (const float*)d_in[12];
    const float* wp0  = (const float*)d_in[13];
    const float* bp0  = (const float*)d_in[14];
    const float* wp1  = (const float*)d_in[15];
    const float* bp1  = (const float*)d_in[16];
    float* out = (float*)d_out;

    cudaFuncSetAttribute(magno_kernel, cudaFuncAttributeMaxDynamicSharedMemorySize, SMEM_BYTES);
    cudaFuncSetAttribute(proj_kernel,  cudaFuncAttributeMaxDynamicSharedMemorySize, PSMEM_BYTES);
    magno_kernel<<<NBLOCK, THREADS, SMEM_BYTES>>>(
        lat, rnd, qry, we0, be0, we1, be1, we2, be2,
        wsw0, bsw0, wsw1, bsw1);
    proj_kernel<<<PGRID, PTHREADS, PSMEM_BYTES>>>(wp0, bp0, wp1, bp1, out);
}

// round 10
// speedup vs baseline: 1.0641x; 1.0641x over previous
#include <cuda_runtime.h>
#include <math.h>

#define FULLMASK 0xffffffffu
typedef unsigned long long u64;

static constexpr int NL     = 2048;
static constexpr int NQ     = 16384;
static constexpr int NB     = 2;
static constexpr int H      = 64;
static constexpr int PH     = 256;
static constexpr int COUT   = 3;
static constexpr int KCAP   = 32;
static constexpr int CAP    = 160;
static constexpr int THREADS= 160;   // 5 warps/CTA
static constexpr int WARPS  = 5;
static constexpr int NBLOCK = 592;   // 148 SMs x 4 CTAs -> 20 warps/SM

// decoded scratch (device global: allocation-free)
__device__ float g_dec[NB * NQ * H];   // 8 MB

// ---- main-kernel shared memory layout (float offsets) ----
static constexpr int OFF_W1    = 0;         // 4096  [64][64], j contiguous
static constexpr int OFF_W2    = 4096;      // 4096
static constexpr int OFF_WE0   = 8192;      // 256   [4][64]
static constexpr int OFF_BE0   = 8448;      // 64
static constexpr int OFF_BE1   = 8512;      // 64
static constexpr int OFF_BE2   = 8576;      // 64
static constexpr int OFF_WSW0  = 8640;      // 32
static constexpr int OFF_BSW0  = 8672;      // 16
static constexpr int OFF_WSW1  = 8688;      // 32
static constexpr int OFF_BSW1  = 8720;      // 2 (+6 pad)
static constexpr int OFF_CAND  = 8728;      // 5 warps x 160 u64 = 1600 floats
static constexpr int SMEM_FLOATS = 10328;
static constexpr int SMEM_BYTES  = SMEM_FLOATS * 4;   // 41312 B x4 = 165KB, 63KB L1D left

// ---------- f32x2 packed helpers ----------
__device__ __forceinline__ u64 pk2(float a, float b) {
    u64 r; asm("mov.b64 %0,{%1,%2};" : "=l"(r) : "f"(a), "f"(b)); return r;
}
__device__ __forceinline__ void upk2(u64 v, float& a, float& b) {
    asm("mov.b64 {%0,%1},%2;" : "=f"(a), "=f"(b) : "l"(v));
}
__device__ __forceinline__ u64 f2fma(u64 a, u64 b, u64 c) {
    u64 d; asm("fma.rn.f32x2 %0,%1,%2,%3;" : "=l"(d) : "l"(a), "l"(b), "l"(c)); return d;
}
__device__ __forceinline__ u64 f2mul(u64 a, u64 b) {
    u64 d; asm("mul.rn.f32x2 %0,%1,%2;" : "=l"(d) : "l"(a), "l"(b)); return d;
}
__device__ __forceinline__ u64 f2add(u64 a, u64 b) {
    u64 d; asm("add.rn.f32x2 %0,%1,%2;" : "=l"(d) : "l"(a), "l"(b)); return d;
}
__device__ __forceinline__ unsigned redux_min_u32(unsigned v) {
    unsigned r; asm("redux.sync.min.u32 %0, %1, 0xffffffff;" : "=r"(r) : "r"(v)); return r;
}

// branch-free gelu: A&S 7.1.26 erf (|abs err| <= 1.5e-7)
__device__ __forceinline__ float gelu_f(float x) {
    float z = fabsf(x) * 0.7071067811865476f;
    float t = __fdividef(1.0f, fmaf(0.3275911f, z, 1.0f));
    float p = t * fmaf(t, fmaf(t, fmaf(t, fmaf(t, 1.061405429f, -1.453152027f),
                                        1.421413741f), -0.284496736f), 0.254829592f);
    float e = __expf(-z * z);
    float er = fmaf(-p, e, 1.0f);
    er = copysignf(er, x);
    return 0.5f * x * (1.0f + er);
}

__device__ __forceinline__ void ce(u64& a, u64& b) {
    u64 lo = a < b ? a : b;
    u64 hi = a < b ? b : a;
    a = lo; b = hi;
}

__global__ void __launch_bounds__(THREADS, 4)
magno_kernel(const float* __restrict__ lat,  const float* __restrict__ rnd,
             const float* __restrict__ qry,
             const float* __restrict__ we0,  const float* __restrict__ be0,
             const float* __restrict__ we1,  const float* __restrict__ be1,
             const float* __restrict__ we2,  const float* __restrict__ be2,
             const float* __restrict__ wsw0, const float* __restrict__ bsw0,
             const float* __restrict__ wsw1, const float* __restrict__ bsw1)
{
    extern __shared__ float sm[];
    const int tid = threadIdx.x;

    for (int t = tid; t < H*H;  t += THREADS) sm[OFF_W1+t]  = we1[t];
    for (int t = tid; t < H*H;  t += THREADS) sm[OFF_W2+t]  = we2[t];
    for (int t = tid; t < 4*H;  t += THREADS) sm[OFF_WE0+t] = we0[t];
    for (int t = tid; t < H;    t += THREADS) sm[OFF_BE0+t] = be0[t];
    for (int t = tid; t < H;    t += THREADS) sm[OFF_BE1+t] = be1[t];
    for (int t = tid; t < H;    t += THREADS) sm[OFF_BE2+t] = be2[t];
    if (tid < 32)              sm[OFF_WSW0+tid]    = wsw0[tid];
    if (tid < 16)              sm[OFF_BSW0+tid]    = bsw0[tid];
    if (tid >= 32 && tid < 64) sm[OFF_WSW1+tid-32] = wsw1[tid-32];
    if (tid >= 64 && tid < 66) sm[OFF_BSW1+tid-64] = bsw1[tid-64];
    __syncthreads();

    const int warp = tid >> 5, lane = tid & 31;
    u64* cand = (u64*)(sm + OFF_CAND) + warp * CAP;
    const float2* latf2 = (const float2*)lat;

    const float R0SQ = (float)(0.055 * 0.055);
    const float R1SQ = (float)(0.11  * 0.11);
    const unsigned lt_mask = (1u << lane) - 1u;

    for (int q = blockIdx.x * WARPS + warp; q < NB * NQ; q += gridDim.x * WARPS) {
        const int  bix = q >> 14;
        const float qx = qry[2*q], qy = qry[2*q+1];

        // ---- per-query scale-mixing weights ----
        float s0 = sm[OFF_BSW1+0], s1 = sm[OFF_BSW1+1];
#pragma unroll
        for (int t = 0; t < 16; t++) {
            float z = sm[OFF_BSW0+t] + qx*sm[OFF_WSW0+t] + qy*sm[OFF_WSW0+16+t];
            z = fmaxf(z, 0.0f);
            s0 = fmaf(z, sm[OFF_WSW1+2*t+0], s0);
            s1 = fmaf(z, sm[OFF_WSW1+2*t+1], s1);
        }
        float mx = fmaxf(s0, s1);
        float e0 = __expf(s0 - mx), e1 = __expf(s1 - mx);
        float inv = __fdividef(1.0f, e0 + e1);
        float sw0v = e0 * inv, sw1v = e1 * inv;

        // ---- radius-filtered candidate collection ----
        int cnt = 0;
        for (int l = lane; l < NL; l += 32) {
            float2 y = __ldg(latf2 + l);
            float dx = qx - y.x, dy = qy - y.y;
            float d2 = __fadd_rn(__fmul_rn(dx, dx), __fmul_rn(dy, dy));
            bool pr = d2 <= R1SQ;
            unsigned m = __ballot_sync(FULLMASK, pr);
            if (pr) {
                int pos = cnt + __popc(m & lt_mask);
                if (pos < CAP)
                    cand[pos] = ((u64)__float_as_uint(d2) << 32) | (unsigned)l;
            }
            cnt += __popc(m);
        }
        if (cnt > CAP) cnt = CAP;
        __syncwarp();

        // ---- exact K=32 smallest selection ----
        u64 mykey = 0x7f7fffff00000000ull;
        int nsel;
        if (cnt <= KCAP) {
            nsel = cnt;
            if (lane < cnt) mykey = cand[lane];
        } else {
            nsel = KCAP;
            u64 c0, c1, c2, c3, c4, c5;
            c0 = (lane       < cnt) ? cand[lane      ] : ~0ull;
            c1 = (lane + 32  < cnt) ? cand[lane + 32 ] : ~0ull;
            c2 = (lane + 64  < cnt) ? cand[lane + 64 ] : ~0ull;
            c3 = (lane + 96  < cnt) ? cand[lane + 96 ] : ~0ull;
            c4 = (lane + 128 < cnt) ? cand[lane + 128] : ~0ull;
            c5 = ~0ull;
            ce(c0,c1); ce(c2,c3); ce(c4,c5);
            ce(c0,c2); ce(c3,c5); ce(c1,c4);
            ce(c0,c1); ce(c2,c3); ce(c4,c5);
            ce(c1,c2); ce(c3,c4); ce(c2,c3);

            unsigned hdb = (unsigned)(c0 >> 32);
#pragma unroll 1
            for (int r = 0; r < KCAP; r++) {
                unsigned m = redux_min_u32(hdb);
                unsigned tied = __ballot_sync(FULLMASK, hdb == m);
                int src;
                if ((tied & (tied - 1u)) == 0u) {
                    src = __ffs(tied) - 1;
                } else {
                    unsigned lw = (hdb == m) ? (unsigned)c0 : 0xffffffffu;
                    unsigned mi = redux_min_u32(lw);
                    src = __ffs(__ballot_sync(FULLMASK, lw == mi)) - 1;
                }
                u64 win = __shfl_sync(FULLMASK, c0, src);
                if (lane == r) mykey = win;
                bool pop = (lane == src);
                c0 = pop ? c1 : c0;
                c1 = pop ? c2 : c1;
                c2 = pop ? c3 : c2;
                c3 = pop ? c4 : c3;
                c4 = pop ? c5 : c4;
                c5 = pop ? ~0ull : c5;
                hdb = (unsigned)(c0 >> 32);
            }
        }
        float seld2  = __uint_as_float((unsigned)(mykey >> 32));
        int   selidx = (int)(mykey & 0xffffffffu);
        if (lane >= nsel) { seld2 = 3.4e38f; selidx = 0; }

        bool v0 = (lane < nsel) && (seld2 <= R0SQ);
        int  c0cnt = __popc(__ballot_sync(FULLMASK, v0));
        float coeff = 0.0f;
        if (v0)          coeff += sw0v / (float)(c0cnt > 1 ? c0cnt : 1);
        if (lane < nsel) coeff += sw1v / (float)(nsel  > 1 ? nsel  : 1);

        const float* frowf = rnd + (size_t)(bix * NL + selidx) * H;
        asm volatile("prefetch.global.L1 [%0];" :: "l"(frowf));
        asm volatile("prefetch.global.L1 [%0];" :: "l"(frowf + 32));

        // ---- layer 0 ----
        float h0[64];
        {
            float2 yc = __ldg(latf2 + selidx);
            u64 yx2 = pk2(yc.x, yc.x), yy2 = pk2(yc.y, yc.y);
            u64 qx2 = pk2(qx, qx),     qy2 = pk2(qy, qy);
            const u64* w0r0 = (const u64*)(sm + OFF_WE0);
            const u64* w0r1 = (const u64*)(sm + OFF_WE0 + 64);
            const u64* w0r2 = (const u64*)(sm + OFF_WE0 + 128);
            const u64* w0r3 = (const u64*)(sm + OFF_WE0 + 192);
            const u64* b0p  = (const u64*)(sm + OFF_BE0);
#pragma unroll
            for (int jp = 0; jp < 32; jp++) {
                u64 t = b0p[jp];
                t = f2fma(yx2, w0r0[jp], t);
                t = f2fma(yy2, w0r1[jp], t);
                t = f2fma(qx2, w0r2[jp], t);
                t = f2fma(qy2, w0r3[jp], t);
                float a, b; upk2(t, a, b);
                h0[2*jp]   = gelu_f(a);
                h0[2*jp+1] = gelu_f(b);
            }
        }

        // ---- layer 1 (channel-tiled x2) ----
        float h1[64];
        {
            const ulonglong2* w1 = (const ulonglong2*)(sm + OFF_W1);
#pragma unroll
            for (int t = 0; t < 2; t++) {
                u64 a[16];
                const u64* b1p = (const u64*)(sm + OFF_BE1) + 8*t;
#pragma unroll
                for (int p = 0; p < 16; p++) a[p] = b1p[p];
#pragma unroll 4
                for (int i = 0; i < 64; i++) {
                    u64 hh = pk2(h0[i], h0[i]);
                    const ulonglong2* row = w1 + i*16 + t*8;
#pragma unroll
                    for (int j2 = 0; j2 < 8; j2++) {
                        ulonglong2 w = row[j2];
                        a[2*j2]   = f2fma(hh, w.x, a[2*j2]);
                        a[2*j2+1] = f2fma(hh, w.y, a[2*j2+1]);
                    }
                }
#pragma unroll
                for (int p = 0; p < 16; p++) {
                    float x, y; upk2(a[p], x, y);
                    h1[32*t + 2*p]   = gelu_f(x);
                    h1[32*t + 2*p+1] = gelu_f(y);
                }
            }
        }

        // ---- layer 2 + f(y)*coeff + butterfly reduce-scatter over neighbors ----
        u64 myd = 0;
        {
            u64 cc = pk2(coeff, coeff);
            const float4* frow = (const float4*)frowf;
            const ulonglong2* w2 = (const ulonglong2*)(sm + OFF_W2);
#pragma unroll
            for (int t = 0; t < 2; t++) {
                u64 a[16];
                const u64* b2p = (const u64*)(sm + OFF_BE2) + 8*t;
#pragma unroll
                for (int p = 0; p < 16; p++) a[p] = b2p[p];
#pragma unroll 4
                for (int i = 0; i < 64; i++) {
                    u64 hh = pk2(h1[i], h1[i]);
                    const ulonglong2* row = w2 + i*16 + t*8;
#pragma unroll
                    for (int j2 = 0; j2 < 8; j2++) {
                        ulonglong2 w = row[j2];
                        a[2*j2]   = f2fma(hh, w.x, a[2*j2]);
                        a[2*j2+1] = f2fma(hh, w.y, a[2*j2+1]);
                    }
                }
#pragma unroll
                for (int p2 = 0; p2 < 8; p2++) {
                    float4 f4 = __ldg(frow + 8*t + p2);
                    a[2*p2]   = f2mul(a[2*p2],   f2mul(pk2(f4.x, f4.y), cc));
                    a[2*p2+1] = f2mul(a[2*p2+1], f2mul(pk2(f4.z, f4.w), cc));
                }
                // butterfly reduce-scatter: 16 accs over 32 lanes, 5 stages
                {
                    bool k3 = (lane >> 3) & 1;
#pragma unroll
                    for (int j = 0; j < 8; j++) {
                        u64 sendv = k3 ? a[j] : a[j+8];
                        u64 recv  = __shfl_xor_sync(FULLMASK, sendv, 8);
                        a[j] = f2add(k3 ? a[j+8] : a[j], recv);
                    }
                    bool k2 = (lane >> 2) & 1;
#pragma unroll
                    for (int j = 0; j < 4; j++) {
                        u64 sendv = k2 ? a[j] : a[j+4];
                        u64 recv  = __shfl_xor_sync(FULLMASK, sendv, 4);
                        a[j] = f2add(k2 ? a[j+4] : a[j], recv);
                    }
                    bool k1 = (lane >> 1) & 1;
#pragma unroll
                    for (int j = 0; j < 2; j++) {
                        u64 sendv = k1 ? a[j] : a[j+2];
                        u64 recv  = __shfl_xor_sync(FULLMASK, sendv, 2);
                        a[j] = f2add(k1 ? a[j+2] : a[j], recv);
                    }
                    bool k0 = lane & 1;
                    {
                        u64 sendv = k0 ? a[0] : a[1];
                        u64 recv  = __shfl_xor_sync(FULLMASK, sendv, 1);
                        a[0] = f2add(k0 ? a[1] : a[0], recv);
                    }
                    a[0] = f2add(a[0], __shfl_xor_sync(FULLMASK, a[0], 16));
                    if ((lane >> 4) == t) myd = a[0];
                }
            }
        }
        // coalesced decoded store: lane l -> channels 2l, 2l+1
        ((u64*)g_dec)[(size_t)q * 32 + lane] = myd;
    }
}

// ======== projection kernel: decoded[64] -> gelu(PH=256) -> COUT=3 ========
// thread-per-row (R8 layout: all SMEM weight reads are warp-uniform broadcasts)
static constexpr int PTHREADS = 128;
static constexpr int PGRID    = NB * NQ / PTHREADS;   // 256

// proj smem layout (floats)
static constexpr int POFF_WP0 = 0;          // 16384  [64][256]
static constexpr int POFF_BP0 = 16384;      // 256
static constexpr int POFF_WP1 = 16640;      // 768    [256][3]
static constexpr int POFF_BP1 = 17408;      // 3 (+1 pad)
static constexpr int PSMEM_FLOATS = 17412;
static constexpr int PSMEM_BYTES  = PSMEM_FLOATS * 4;   // 69648 B

__global__ void __launch_bounds__(PTHREADS)
proj_kernel(const float* __restrict__ wp0, const float* __restrict__ bp0,
            const float* __restrict__ wp1, const float* __restrict__ bp1,
            float* __restrict__ out)
{
    extern __shared__ float psm[];
    const int tid = threadIdx.x;
    for (int t = tid; t < H*PH;    t += PTHREADS) psm[POFF_WP0+t] = wp0[t];
    for (int t = tid; t < PH;      t += PTHREADS) psm[POFF_BP0+t] = bp0[t];
    for (int t = tid; t < PH*COUT; t += PTHREADS) psm[POFF_WP1+t] = wp1[t];
    if (tid < COUT) psm[POFF_BP1+tid] = bp1[tid];
    __syncthreads();

    const int row = blockIdx.x * PTHREADS + tid;

    // decoded row in registers
    float dec[64];
    {
        const float4* dp = (const float4*)(g_dec + (size_t)row * H);
#pragma unroll
        for (int i = 0; i < 16; i++) {
            float4 v = dp[i];
            dec[4*i+0] = v.x; dec[4*i+1] = v.y;
            dec[4*i+2] = v.z; dec[4*i+3] = v.w;
        }
    }

    float o0 = psm[POFF_BP1+0], o1 = psm[POFF_BP1+1], o2 = psm[POFF_BP1+2];

#pragma unroll 1
    for (int ch = 0; ch < 4; ch++) {           // 4 chunks of 64 hidden
        u64 a[32];
        {
            const u64* bp = (const u64*)(psm + POFF_BP0 + ch * 64);
#pragma unroll
            for (int p = 0; p < 32; p++) a[p] = bp[p];
        }
#pragma unroll 4
        for (int i = 0; i < 64; i++) {
            u64 dd = pk2(dec[i], dec[i]);
            const ulonglong2* wr =
                (const ulonglong2*)(psm + POFF_WP0 + (size_t)i * PH + ch * 64);
#pragma unroll
            for (int j2 = 0; j2 < 16; j2++) {
                ulonglong2 w = wr[j2];          // LDS.128 warp-uniform broadcast
                a[2*j2]   = f2fma(dd, w.x, a[2*j2]);
                a[2*j2+1] = f2fma(dd, w.y, a[2*j2+1]);
            }
        }
#pragma unroll
        for (int p = 0; p < 32; p++) {
            float x, y; upk2(a[p], x, y);
            float g0 = gelu_f(x), g1 = gelu_f(y);
            int jj = ch * 64 + 2 * p;
            o0 = fmaf(g0, psm[POFF_WP1 + jj*3 + 0], o0);
            o1 = fmaf(g0, psm[POFF_WP1 + jj*3 + 1], o1);
            o2 = fmaf(g0, psm[POFF_WP1 + jj*3 + 2], o2);
            o0 = fmaf(g1, psm[POFF_WP1 + jj*3 + 3], o0);
            o1 = fmaf(g1, psm[POFF_WP1 + jj*3 + 4], o1);
            o2 = fmaf(g1, psm[POFF_WP1 + jj*3 + 5], o2);
        }
    }

    out[row*3 + 0] = o0;
    out[row*3 + 1] = o1;
    out[row*3 + 2] = o2;
}

extern "C" void kernel_launch(void* const* d_in, const int* in_sizes, int n_in,
                              void* d_out, int out_size) {
    const float* lat  = (const float*)d_in[0];
    const float* rnd  = (const float*)d_in[1];
    const float* qry  = (const float*)d_in[2];
    const float* we0  = (const float*)d_in[3];
    const float* be0  = (const float*)d_in[4];
    const float* we1  = (const float*)d_in[5];
    const float* be1  = (const float*)d_in[6];
    const float* we2  = (const float*)d_in[7];
    const float* be2  = (const float*)d_in[8];
    const float* wsw0 = (const float*)d_in[9];
    const float* bsw0 = (const float*)d_in[10];
    const float* wsw1 = (const float*)d_in[11];
    const float* bsw1 = (const float*)d_in[12];
    const float* wp0  = (const float*)d_in[13];
    const float* bp0  = (const float*)d_in[14];
    const float* wp1  = (const float*)d_in[15];
    const float* bp1  = (const float*)d_in[16];
    float* out = (float*)d_out;

    cudaFuncSetAttribute(magno_kernel, cudaFuncAttributeMaxDynamicSharedMemorySize, SMEM_BYTES);
    cudaFuncSetAttribute(proj_kernel,  cudaFuncAttributeMaxDynamicSharedMemorySize, PSMEM_BYTES);
    magno_kernel<<<NBLOCK, THREADS, SMEM_BYTES>>>(
        lat, rnd, qry, we0, be0, we1, be1, we2, be2,
        wsw0, bsw0, wsw1, bsw1);
    proj_kernel<<<PGRID, PTHREADS, PSMEM_BYTES>>>(wp0, bp0, wp1, bp1, out);
}

// round 12
// speedup vs baseline: 1.4573x; 1.3695x over previous
#include <cuda_runtime.h>
#include <cuda_bf16.h>
#include <math.h>
#include <cstdint>

#define FULLMASK 0xffffffffu
typedef unsigned long long u64;

static constexpr int NL     = 2048;
static constexpr int NQ     = 16384;
static constexpr int NB     = 2;
static constexpr int H      = 64;
static constexpr int PH     = 256;
static constexpr int COUT   = 3;
static constexpr int KCAP   = 32;
static constexpr int CAP    = 160;
static constexpr int THREADS= 128;
static constexpr int WARPS  = 4;
static constexpr int NBLOCK = 444;   // 148 SMs x 3 CTAs

// decoded scratch
__device__ float g_dec[NB * NQ * H];   // 8 MB

// ---- main-kernel SMEM byte offsets ----
static constexpr int OFF_ASTG  = 0;       // 4 warps x 4096 (A staging, swizzled) = 16384
static constexpr int OFF_FRAGB = 16384;   // 4 arrays x 1024 u64 (B fragments)    = 32768
static constexpr int OFF_CAND  = 49152;   // 4 warps x 160 u64                    = 5120
static constexpr int OFF_WE0   = 54272;   // 256 f32 = 1024B
static constexpr int OFF_BE0   = 55296;   // 64 f32
static constexpr int OFF_BE1   = 55552;   // 64 f32 (read as float2 pairs)
static constexpr int OFF_BE2   = 55808;   // 64 f32
static constexpr int OFF_WSW0  = 56064;   // 32 f32
static constexpr int OFF_BSW0  = 56192;   // 16 f32
static constexpr int OFF_WSW1  = 56256;   // 32 f32
static constexpr int OFF_BSW1  = 56384;   // 2 f32
static constexpr int SMEM_BYTES= 56576;   // x3 CTAs = 170KB; L1D carveout ~58KB

// ---------- helpers ----------
__device__ __forceinline__ uint32_t smem_to_u32(const void* p) {
    uint32_t a;
    asm("{ .reg .u64 t; cvta.to.shared.u64 t, %1; cvt.u32.u64 %0, t; }" : "=r"(a) : "l"(p));
    return a;
}
// pack two f32 -> bf16x2 (lo = first element / even k, hi = odd k)
__device__ __forceinline__ uint32_t pkbf(float lo, float hi) {
    uint32_t r; asm("cvt.rn.bf16x2.f32 %0, %1, %2;" : "=r"(r) : "f"(hi), "f"(lo)); return r;
}
__device__ __forceinline__ float lof(float x) {
    return x - __bfloat162float(__float2bfloat16(x));
}
__device__ __forceinline__ void hmma(float c[4], const uint32_t a[4], uint32_t b0, uint32_t b1) {
    asm volatile("mma.sync.aligned.m16n8k16.row.col.f32.bf16.bf16.f32 "
        "{%0,%1,%2,%3}, {%4,%5,%6,%7}, {%8,%9}, {%0,%1,%2,%3};"
        : "+f"(c[0]), "+f"(c[1]), "+f"(c[2]), "+f"(c[3])
        : "r"(a[0]), "r"(a[1]), "r"(a[2]), "r"(a[3]), "r"(b0), "r"(b1));
}
__device__ __forceinline__ void ldsm4(uint32_t r[4], uint32_t addr) {
    asm volatile("ldmatrix.sync.aligned.m8n8.x4.shared.b16 {%0,%1,%2,%3}, [%4];"
        : "=r"(r[0]), "=r"(r[1]), "=r"(r[2]), "=r"(r[3]) : "r"(addr));
}
__device__ __forceinline__ u64 pk2(float a, float b) {
    u64 r; asm("mov.b64 %0,{%1,%2};" : "=l"(r) : "f"(a), "f"(b)); return r;
}
__device__ __forceinline__ void upk2(u64 v, float& a, float& b) {
    asm("mov.b64 {%0,%1},%2;" : "=f"(a), "=f"(b) : "l"(v));
}
__device__ __forceinline__ u64 f2fma(u64 a, u64 b, u64 c) {
    u64 d; asm("fma.rn.f32x2 %0,%1,%2,%3;" : "=l"(d) : "l"(a), "l"(b), "l"(c)); return d;
}
__device__ __forceinline__ u64 f2add(u64 a, u64 b) {
    u64 d; asm("add.rn.f32x2 %0,%1,%2;" : "=l"(d) : "l"(a), "l"(b)); return d;
}
__device__ __forceinline__ unsigned redux_min_u32(unsigned v) {
    unsigned r; asm("redux.sync.min.u32 %0, %1, 0xffffffff;" : "=r"(r) : "r"(v)); return r;
}
__device__ __forceinline__ float gelu_f(float x) {
    float z = fabsf(x) * 0.7071067811865476f;
    float t = __fdividef(1.0f, fmaf(0.3275911f, z, 1.0f));
    float p = t * fmaf(t, fmaf(t, fmaf(t, fmaf(t, 1.061405429f, -1.453152027f),
                                        1.421413741f), -0.284496736f), 0.254829592f);
    float e = __expf(-z * z);
    float er = fmaf(-p, e, 1.0f);
    er = copysignf(er, x);
    return 0.5f * x * (1.0f + er);
}
__device__ __forceinline__ void ce(u64& a, u64& b) {
    u64 lo = a < b ? a : b;
    u64 hi = a < b ? b : a;
    a = lo; b = hi;
}

__global__ void __launch_bounds__(THREADS, 3)
magno_kernel(const float* __restrict__ lat,  const float* __restrict__ rnd,
             const float* __restrict__ qry,
             const float* __restrict__ we0,  const float* __restrict__ be0,
             const float* __restrict__ we1,  const float* __restrict__ be1,
             const float* __restrict__ we2,  const float* __restrict__ be2,
             const float* __restrict__ wsw0, const float* __restrict__ bsw0,
             const float* __restrict__ wsw1, const float* __restrict__ bsw1)
{
    extern __shared__ char smem[];
    const uint32_t smem_base = smem_to_u32(smem);
    const int tid = threadIdx.x, warp = tid >> 5, lane = tid & 31;

    // ---- B fragments: arrays 0=W1hi 1=W1lo 2=W2hi 3=W2lo ----
    // frag (kt,nt): lane l holds reg0={W[k0][n],W[k0+1][n]}, reg1={W[k0+8][n],W[k0+9][n]}
    // k0 = kt*16 + 2*(l&3), n = nt*8 + (l>>2)
    {
        u64* fb = (u64*)(smem + OFF_FRAGB);
        for (int i = tid; i < 4096; i += THREADS) {
            int arr = i >> 10, rem = i & 1023;
            int frag = rem >> 5, l = rem & 31;
            int kt = frag >> 3, nt = frag & 7;
            int k0 = kt*16 + 2*(l & 3);
            int n  = nt*8 + (l >> 2);
            const float* W = (arr < 2) ? we1 : we2;
            float w00 = W[(k0  )*H + n], w01 = W[(k0+1)*H + n];
            float w10 = W[(k0+8)*H + n], w11 = W[(k0+9)*H + n];
            if (arr & 1) { w00 = lof(w00); w01 = lof(w01); w10 = lof(w10); w11 = lof(w11); }
            uint32_t r0 = pkbf(w00, w01);
            uint32_t r1 = pkbf(w10, w11);
            fb[i] = (u64)r0 | ((u64)r1 << 32);
        }
    }
    {
        float* f = (float*)smem;
        for (int t = tid; t < 4*H; t += THREADS) f[OFF_WE0/4 + t] = we0[t];
        for (int t = tid; t < H;   t += THREADS) {
            f[OFF_BE0/4 + t] = be0[t];
            f[OFF_BE1/4 + t] = be1[t];
            f[OFF_BE2/4 + t] = be2[t];
        }
        if (tid < 32)              f[OFF_WSW0/4 + tid]    = wsw0[tid];
        if (tid < 16)              f[OFF_BSW0/4 + tid]    = bsw0[tid];
        if (tid >= 32 && tid < 64) f[OFF_WSW1/4 + tid-32] = wsw1[tid-32];
        if (tid >= 64 && tid < 66) f[OFF_BSW1/4 + tid-64] = bsw1[tid-64];
    }
    __syncthreads();

    u64* cand = (u64*)(smem + OFF_CAND) + warp * CAP;
    const u64* fb = (const u64*)(smem + OFF_FRAGB);
    const float2* latf2 = (const float2*)lat;
    const float* smf = (const float*)smem;
    char* astg = smem + OFF_ASTG + warp * 4096;
    const uint32_t astg_u32 = smem_base + OFF_ASTG + warp * 4096;

    const float R0SQ = (float)(0.055 * 0.055);
    const float R1SQ = (float)(0.11  * 0.11);
    const unsigned lt_mask = (1u << lane) - 1u;

    for (int q = blockIdx.x * WARPS + warp; q < NB * NQ; q += gridDim.x * WARPS) {
        const int  bix = q >> 14;
        const float qx = qry[2*q], qy = qry[2*q+1];

        // ---- scale-mixing weights ----
        float s0 = smf[OFF_BSW1/4+0], s1 = smf[OFF_BSW1/4+1];
#pragma unroll
        for (int t = 0; t < 16; t++) {
            float z = smf[OFF_BSW0/4+t] + qx*smf[OFF_WSW0/4+t] + qy*smf[OFF_WSW0/4+16+t];
            z = fmaxf(z, 0.0f);
            s0 = fmaf(z, smf[OFF_WSW1/4+2*t+0], s0);
            s1 = fmaf(z, smf[OFF_WSW1/4+2*t+1], s1);
        }
        float mx = fmaxf(s0, s1);
        float e0 = __expf(s0 - mx), e1 = __expf(s1 - mx);
        float inv = __fdividef(1.0f, e0 + e1);
        float sw0v = e0 * inv, sw1v = e1 * inv;

        // ---- candidate collection ----
        int cnt = 0;
        for (int l = lane; l < NL; l += 32) {
            float2 y = __ldg(latf2 + l);
            float dx = qx - y.x, dy = qy - y.y;
            float d2 = __fadd_rn(__fmul_rn(dx, dx), __fmul_rn(dy, dy));
            bool pr = d2 <= R1SQ;
            unsigned m = __ballot_sync(FULLMASK, pr);
            if (pr) {
                int pos = cnt + __popc(m & lt_mask);
                if (pos < CAP)
                    cand[pos] = ((u64)__float_as_uint(d2) << 32) | (unsigned)l;
            }
            cnt += __popc(m);
        }
        if (cnt > CAP) cnt = CAP;
        __syncwarp();

        // ---- exact K=32 selection ----
        u64 mykey = 0x7f7fffff00000000ull;
        int nsel;
        if (cnt <= KCAP) {
            nsel = cnt;
            if (lane < cnt) mykey = cand[lane];
        } else {
            nsel = KCAP;
            u64 c0, c1, c2, c3, c4, c5;
            c0 = (lane       < cnt) ? cand[lane      ] : ~0ull;
            c1 = (lane + 32  < cnt) ? cand[lane + 32 ] : ~0ull;
            c2 = (lane + 64  < cnt) ? cand[lane + 64 ] : ~0ull;
            c3 = (lane + 96  < cnt) ? cand[lane + 96 ] : ~0ull;
            c4 = (lane + 128 < cnt) ? cand[lane + 128] : ~0ull;
            c5 = ~0ull;
            ce(c0,c1); ce(c2,c3); ce(c4,c5);
            ce(c0,c2); ce(c3,c5); ce(c1,c4);
            ce(c0,c1); ce(c2,c3); ce(c4,c5);
            ce(c1,c2); ce(c3,c4); ce(c2,c3);
            unsigned hdb = (unsigned)(c0 >> 32);
#pragma unroll 1
            for (int r = 0; r < KCAP; r++) {
                unsigned m = redux_min_u32(hdb);
                unsigned tied = __ballot_sync(FULLMASK, hdb == m);
                int src;
                if ((tied & (tied - 1u)) == 0u) {
                    src = __ffs(tied) - 1;
                } else {
                    unsigned lw = (hdb == m) ? (unsigned)c0 : 0xffffffffu;
                    unsigned mi = redux_min_u32(lw);
                    src = __ffs(__ballot_sync(FULLMASK, lw == mi)) - 1;
                }
                u64 win = __shfl_sync(FULLMASK, c0, src);
                if (lane == r) mykey = win;
                bool pop = (lane == src);
                c0 = pop ? c1 : c0; c1 = pop ? c2 : c1; c2 = pop ? c3 : c2;
                c3 = pop ? c4 : c3; c4 = pop ? c5 : c4; c5 = pop ? ~0ull : c5;
                hdb = (unsigned)(c0 >> 32);
            }
        }
        float seld2  = __uint_as_float((unsigned)(mykey >> 32));
        int   selidx = (int)(mykey & 0xffffffffu);
        if (lane >= nsel) { seld2 = 3.4e38f; selidx = 0; }

        bool v0 = (lane < nsel) && (seld2 <= R0SQ);
        int  c0cnt = __popc(__ballot_sync(FULLMASK, v0));
        float coeff = 0.0f;
        if (v0)          coeff += sw0v / (float)(c0cnt > 1 ? c0cnt : 1);
        if (lane < nsel) coeff += sw1v / (float)(nsel  > 1 ? nsel  : 1);

        {
            const float* frowf = rnd + (size_t)(bix * NL + selidx) * H;
            asm volatile("prefetch.global.L1 [%0];" :: "l"(frowf));
            asm volatile("prefetch.global.L1 [%0];" :: "l"(frowf + 32));
        }

        // ---- layer 0 (lane = neighbor row), pack bf16 hi/lo ----
        uint32_t hiP[32], loP[32];
        {
            float2 yc = __ldg(latf2 + selidx);
            u64 yx2 = pk2(yc.x, yc.x), yy2 = pk2(yc.y, yc.y);
            u64 qx2 = pk2(qx, qx),     qy2 = pk2(qy, qy);
            const u64* w0r0 = (const u64*)(smem + OFF_WE0);
            const u64* w0r1 = (const u64*)(smem + OFF_WE0 + 256);
            const u64* w0r2 = (const u64*)(smem + OFF_WE0 + 512);
            const u64* w0r3 = (const u64*)(smem + OFF_WE0 + 768);
            const u64* b0p  = (const u64*)(smem + OFF_BE0);
#pragma unroll
            for (int jp = 0; jp < 32; jp++) {
                u64 t = b0p[jp];
                t = f2fma(yx2, w0r0[jp], t);
                t = f2fma(yy2, w0r1[jp], t);
                t = f2fma(qx2, w0r2[jp], t);
                t = f2fma(qy2, w0r3[jp], t);
                float a, b; upk2(t, a, b);
                float g0 = gelu_f(a), g1 = gelu_f(b);
                hiP[jp] = pkbf(g0, g1);
                loP[jp] = pkbf(lof(g0), lof(g1));
            }
        }

        // ---- stage hi/lo, ldmatrix A fragments ----
        uint32_t Ahi[2][4][4], Alo[2][4][4];
        __syncwarp();
#pragma unroll
        for (int c = 0; c < 8; c++) {
            uint32_t off = (uint32_t)(lane*128 + ((c ^ (lane & 7)) << 4));
            *(uint4*)(astg + off) = make_uint4(hiP[4*c], hiP[4*c+1], hiP[4*c+2], hiP[4*c+3]);
        }
        __syncwarp();
#pragma unroll
        for (int mt = 0; mt < 2; mt++)
#pragma unroll
            for (int kt = 0; kt < 4; kt++) {
                int row = mt*16 + (lane & 15);
                int chunk = 2*kt + (lane >> 4);
                ldsm4(Ahi[mt][kt], astg_u32 + row*128 + ((chunk ^ (row & 7)) << 4));
            }
        __syncwarp();
#pragma unroll
        for (int c = 0; c < 8; c++) {
            uint32_t off = (uint32_t)(lane*128 + ((c ^ (lane & 7)) << 4));
            *(uint4*)(astg + off) = make_uint4(loP[4*c], loP[4*c+1], loP[4*c+2], loP[4*c+3]);
        }
        __syncwarp();
#pragma unroll
        for (int mt = 0; mt < 2; mt++)
#pragma unroll
            for (int kt = 0; kt < 4; kt++) {
                int row = mt*16 + (lane & 15);
                int chunk = 2*kt + (lane >> 4);
                ldsm4(Alo[mt][kt], astg_u32 + row*128 + ((chunk ^ (row & 7)) << 4));
            }

        // ---- layer 1: acc = Ahi*W1hi + Alo*W1hi + Ahi*W1lo ----
        float acc[2][8][4];
#pragma unroll
        for (int mt = 0; mt < 2; mt++)
#pragma unroll
            for (int nt = 0; nt < 8; nt++)
#pragma unroll
                for (int r = 0; r < 4; r++) acc[mt][nt][r] = 0.0f;

#define PASS(AREG, ARR) \
        _Pragma("unroll") \
        for (int kt = 0; kt < 4; kt++) { \
            u64 bf[8]; \
            _Pragma("unroll") \
            for (int nt = 0; nt < 8; nt++) bf[nt] = fb[(ARR)*1024 + (kt*8+nt)*32 + lane]; \
            _Pragma("unroll") \
            for (int mt = 0; mt < 2; mt++) \
            _Pragma("unroll") \
            for (int nt = 0; nt < 8; nt++) \
                hmma(acc[mt][nt], AREG[mt][kt], (uint32_t)bf[nt], (uint32_t)(bf[nt] >> 32)); \
        }

        PASS(Ahi, 0)
        PASS(Alo, 0)
        PASS(Ahi, 1)

        // ---- bias + gelu + re-fragment (C-frag -> A-frag, register-exact) ----
        uint32_t A2hi[2][4][4], A2lo[2][4][4];
        {
            const float2* b1p = (const float2*)(smem + OFF_BE1);
#pragma unroll
            for (int mt = 0; mt < 2; mt++)
#pragma unroll
                for (int j = 0; j < 4; j++)
#pragma unroll
                    for (int s = 0; s < 2; s++) {
                        int nt = 2*j + s;
                        float2 bb = b1p[nt*4 + (lane & 3)];
                        float g0 = gelu_f(acc[mt][nt][0] + bb.x);
                        float g1 = gelu_f(acc[mt][nt][1] + bb.y);
                        float g2 = gelu_f(acc[mt][nt][2] + bb.x);
                        float g3 = gelu_f(acc[mt][nt][3] + bb.y);
                        A2hi[mt][j][2*s]   = pkbf(g0, g1);
                        A2hi[mt][j][2*s+1] = pkbf(g2, g3);
                        A2lo[mt][j][2*s]   = pkbf(lof(g0), lof(g1));
                        A2lo[mt][j][2*s+1] = pkbf(lof(g2), lof(g3));
                    }
        }

        // ---- layer 2 ----
#pragma unroll
        for (int mt = 0; mt < 2; mt++)
#pragma unroll
            for (int nt = 0; nt < 8; nt++)
#pragma unroll
                for (int r = 0; r < 4; r++) acc[mt][nt][r] = 0.0f;

        PASS(A2hi, 2)
        PASS(A2lo, 2)
        PASS(A2hi, 3)
#undef PASS

        // ---- epilogue in fragment layout ----
        {
            float cf[2][2]; int si[2][2];
#pragma unroll
            for (int mt = 0; mt < 2; mt++)
#pragma unroll
                for (int hf = 0; hf < 2; hf++) {
                    int src = mt*16 + (lane >> 2) + 8*hf;
                    cf[mt][hf] = __shfl_sync(FULLMASK, coeff,  src);
                    si[mt][hf] = __shfl_sync(FULLMASK, selidx, src);
                }
            const float* rb = rnd + (size_t)bix * NL * H;
            const float2* b2p = (const float2*)(smem + OFF_BE2);
            u64 red[8];
#pragma unroll
            for (int nt = 0; nt < 8; nt++) {
                float2 bb = b2p[nt*4 + (lane & 3)];
                int colb = nt*8 + 2*(lane & 3);
                float sx = 0.f, sy = 0.f;
#pragma unroll
                for (int mt = 0; mt < 2; mt++)
#pragma unroll
                    for (int hf = 0; hf < 2; hf++) {
                        float2 fy = __ldg((const float2*)(rb + (size_t)si[mt][hf]*H + colb));
                        float cfv = cf[mt][hf];
                        sx += (acc[mt][nt][2*hf+0] + bb.x) * fy.x * cfv;
                        sy += (acc[mt][nt][2*hf+1] + bb.y) * fy.y * cfv;
                    }
                u64 v = pk2(sx, sy);
                v = f2add(v, __shfl_xor_sync(FULLMASK, v, 4));
                v = f2add(v, __shfl_xor_sync(FULLMASK, v, 8));
                v = f2add(v, __shfl_xor_sync(FULLMASK, v, 16));
                red[nt] = v;
            }
            u64 myd = red[0];
#pragma unroll
            for (int nt = 1; nt < 8; nt++)
                if ((lane >> 2) == nt) myd = red[nt];
            ((u64*)g_dec)[(size_t)q * 32 + lane] = myd;
        }
    }
}

// ======== projection kernel (R10-best, unchanged) ========
static constexpr int PTHREADS = 128;
static constexpr int PGRID    = NB * NQ / PTHREADS;   // 256
static constexpr int POFF_WP0 = 0;
static constexpr int POFF_BP0 = 16384;
static constexpr int POFF_WP1 = 16640;
static constexpr int POFF_BP1 = 17408;
static constexpr int PSMEM_FLOATS = 17412;
static constexpr int PSMEM_BYTES  = PSMEM_FLOATS * 4;

__global__ void __launch_bounds__(PTHREADS)
proj_kernel(const float* __restrict__ wp0, const float* __restrict__ bp0,
            const float* __restrict__ wp1, const float* __restrict__ bp1,
            float* __restrict__ out)
{
    extern __shared__ float psm[];
    const int tid = threadIdx.x;
    for (int t = tid; t < H*PH;    t += PTHREADS) psm[POFF_WP0+t] = wp0[t];
    for (int t = tid; t < PH;      t += PTHREADS) psm[POFF_BP0+t] = bp0[t];
    for (int t = tid; t < PH*COUT; t += PTHREADS) psm[POFF_WP1+t] = wp1[t];
    if (tid < COUT) psm[POFF_BP1+tid] = bp1[tid];
    __syncthreads();

    const int row = blockIdx.x * PTHREADS + tid;
    float dec[64];
    {
        const float4* dp = (const float4*)(g_dec + (size_t)row * H);
#pragma unroll
        for (int i = 0; i < 16; i++) {
            float4 v = dp[i];
            dec[4*i+0] = v.x; dec[4*i+1] = v.y;
            dec[4*i+2] = v.z; dec[4*i+3] = v.w;
        }
    }
    float o0 = psm[POFF_BP1+0], o1 = psm[POFF_BP1+1], o2 = psm[POFF_BP1+2];
#pragma unroll 1
    for (int ch = 0; ch < 4; ch++) {
        u64 a[32];
        {
            const u64* bp = (const u64*)(psm + POFF_BP0 + ch * 64);
#pragma unroll
            for (int p = 0; p < 32; p++) a[p] = bp[p];
        }
#pragma unroll 4
        for (int i = 0; i < 64; i++) {
            u64 dd = pk2(dec[i], dec[i]);
            const ulonglong2* wr =
                (const ulonglong2*)(psm + POFF_WP0 + (size_t)i * PH + ch * 64);
#pragma unroll
            for (int j2 = 0; j2 < 16; j2++) {
                ulonglong2 w = wr[j2];
                a[2*j2]   = f2fma(dd, w.x, a[2*j2]);
                a[2*j2+1] = f2fma(dd, w.y, a[2*j2+1]);
            }
        }
#pragma unroll
        for (int p = 0; p < 32; p++) {
            float x, y; upk2(a[p], x, y);
            float g0 = gelu_f(x), g1 = gelu_f(y);
            int jj = ch * 64 + 2 * p;
            o0 = fmaf(g0, psm[POFF_WP1 + jj*3 + 0], o0);
            o1 = fmaf(g0, psm[POFF_WP1 + jj*3 + 1], o1);
            o2 = fmaf(g0, psm[POFF_WP1 + jj*3 + 2], o2);
            o0 = fmaf(g1, psm[POFF_WP1 + jj*3 + 3], o0);
            o1 = fmaf(g1, psm[POFF_WP1 + jj*3 + 4], o1);
            o2 = fmaf(g1, psm[POFF_WP1 + jj*3 + 5], o2);
        }
    }
    out[row*3 + 0] = o0;
    out[row*3 + 1] = o1;
    out[row*3 + 2] = o2;
}

extern "C" void kernel_launch(void* const* d_in, const int* in_sizes, int n_in,
                              void* d_out, int out_size) {
    const float* lat  = (const float*)d_in[0];
    const float* rnd  = (const float*)d_in[1];
    const float* qry  = (const float*)d_in[2];
    const float* we0  = (const float*)d_in[3];
    const float* be0  = (const float*)d_in[4];
    const float* we1  = (const float*)d_in[5];
    const float* be1  = (const float*)d_in[6];
    const float* we2  = (const float*)d_in[7];
    const float* be2  = (const float*)d_in[8];
    const float* wsw0 = (const float*)d_in[9];
    const float* bsw0 = (const float*)d_in[10];
    const float* wsw1 = (const float*)d_in[11];
    const float* bsw1 = (const float*)d_in[12];
    const float* wp0  = (const float*)d_in[13];
    const float* bp0  = (const float*)d_in[14];
    const float* wp1  = (const float*)d_in[15];
    const float* bp1  = (const float*)d_in[16];
    float* out = (float*)d_out;

    cudaFuncSetAttribute(magno_kernel, cudaFuncAttributeMaxDynamicSharedMemorySize, SMEM_BYTES);
    cudaFuncSetAttribute(proj_kernel,  cudaFuncAttributeMaxDynamicSharedMemorySize, PSMEM_BYTES);
    magno_kernel<<<NBLOCK, THREADS, SMEM_BYTES>>>(
        lat, rnd, qry, we0, be0, we1, be1, we2, be2,
        wsw0, bsw0, wsw1, bsw1);
    proj_kernel<<<PGRID, PTHREADS, PSMEM_BYTES>>>(wp0, bp0, wp1, bp1, out);
}